// round 14
// baseline (speedup 1.0000x reference)
#include <cuda_runtime.h>
#include <cuda_bf16.h>
#include <math.h>

// Problem constants
#define B_   64
#define T_   512
#define H_   50
#define G_   200      // 4*H
#define F_   513
#define M_   (B_*T_)  // 32768
#define KP3  64       // H padded for gemm3 A rows

// GEMM1: N padded to 224 (2 n-CTAs x 112), K=512 via 32 k16 steps + fp32 rank-1 fixup (col 512)
#define G1_KS 32
#define G1_NT 28
// GEMM3: N padded to 560 (5 n-CTAs x 112), K=64 -> 4 k16 steps
#define G3_KS 4
#define G3_NT 70

// Scratch (device globals)
__device__ float  g_xg[(size_t)M_ * G_];
__device__ float  g_hs[(size_t)M_ * KP3];
__device__ uint4  g_b1[G1_KS * G1_NT * 32];
__device__ uint4  g_b3[G3_KS * G3_NT * 32];
__device__ float2 g_tail1[224];
__device__ float2 g_tail3[560];

typedef unsigned long long u64;

// ---------------- f32x2 helpers ----------------
__device__ __forceinline__ u64 pk2(float lo, float hi) {
    u64 r; asm("mov.b64 %0, {%1, %2};" : "=l"(r) : "f"(lo), "f"(hi)); return r;
}
__device__ __forceinline__ void upk2(u64 v, float& lo, float& hi) {
    asm("mov.b64 {%0, %1}, %2;" : "=f"(lo), "=f"(hi) : "l"(v));
}
__device__ __forceinline__ void fma2(u64& d, u64 a, u64 b) {
    asm("fma.rn.f32x2 %0, %1, %2, %0;" : "+l"(d) : "l"(a), "l"(b));
}
__device__ __forceinline__ void add2(u64& d, u64 a) {
    asm("add.rn.f32x2 %0, %0, %1;" : "+l"(d) : "l"(a));
}

// ---------------- bf16 split helpers ----------------
__device__ __forceinline__ void split2(float v0, float v1, unsigned& h, unsigned& l) {
    __nv_bfloat162 bh = __float22bfloat162_rn(make_float2(v0, v1));
    h = *(unsigned*)&bh;
    float f0 = __uint_as_float(h << 16);
    float f1 = __uint_as_float(h & 0xffff0000u);
    __nv_bfloat162 bl = __float22bfloat162_rn(make_float2(v0 - f0, v1 - f1));
    l = *(unsigned*)&bl;
}

// ---------------- warp MMA m16n8k16 bf16 ----------------
__device__ __forceinline__ void mma16816(float* d, const unsigned* a,
                                         unsigned b0, unsigned b1) {
    asm volatile(
        "mma.sync.aligned.m16n8k16.row.col.f32.bf16.bf16.f32 "
        "{%0,%1,%2,%3}, {%4,%5,%6,%7}, {%8,%9}, {%0,%1,%2,%3};"
        : "+f"(d[0]), "+f"(d[1]), "+f"(d[2]), "+f"(d[3])
        : "r"(a[0]), "r"(a[1]), "r"(a[2]), "r"(a[3]), "r"(b0), "r"(b1));
}

// ---------------- prepass: pack B fragments ----------------
__global__ void pack_b1(const float* __restrict__ wih, uint4* __restrict__ bp,
                        const float* __restrict__ bih, float2* __restrict__ tail)
{
    int idx = blockIdx.x * 256 + threadIdx.x;
    if (idx < 224)
        tail[idx] = (idx < G_) ? make_float2(wih[idx * F_ + 512], bih[idx])
                               : make_float2(0.f, 0.f);
    if (idx >= G1_KS * G1_NT * 32) return;
    int kt   = idx / (G1_NT * 32);
    int rem  = idx - kt * (G1_NT * 32);
    int lane = rem & 31;
    int nt   = rem >> 5;
    int n    = nt * 8 + (lane >> 2);
    int k0   = kt * 16 + (lane & 3) * 2;
    float v0 = 0.f, v1 = 0.f, v2 = 0.f, v3 = 0.f;
    if (n < G_) {
        const float* wr = wih + (size_t)n * F_;
        v0 = wr[k0]; v1 = wr[k0 + 1]; v2 = wr[k0 + 8]; v3 = wr[k0 + 9];
    }
    unsigned h0, l0, h1, l1;
    split2(v0, v1, h0, l0);
    split2(v2, v3, h1, l1);
    bp[idx] = make_uint4(h0, h1, l0, l1);
}

__global__ void pack_b3(const float* __restrict__ wout, uint4* __restrict__ bp,
                        const float* __restrict__ bout, float2* __restrict__ tail)
{
    int idx = blockIdx.x * 256 + threadIdx.x;
    if (idx < 560)
        tail[idx] = make_float2(0.f, (idx < F_) ? bout[idx] : 0.f);
    if (idx >= G3_KS * G3_NT * 32) return;
    int kt   = idx / (G3_NT * 32);
    int rem  = idx - kt * (G3_NT * 32);
    int lane = rem & 31;
    int nt   = rem >> 5;
    int n    = nt * 8 + (lane >> 2);
    int k0   = kt * 16 + (lane & 3) * 2;
    float v0 = 0.f, v1 = 0.f, v2 = 0.f, v3 = 0.f;
    if (n < F_) {
        const float* wr = wout + (size_t)n * H_;
        if (k0     < H_) v0 = wr[k0];
        if (k0 + 1 < H_) v1 = wr[k0 + 1];
        if (k0 + 8 < H_) v2 = wr[k0 + 8];
        if (k0 + 9 < H_) v3 = wr[k0 + 9];
    }
    unsigned h0, l0, h1, l1;
    split2(v0, v1, h0, l0);
    split2(v2, v3, h1, l1);
    bp[idx] = make_uint4(h0, h1, l0, l1);
}

// zero hs pad columns [H_, KP3) once (gemm3 reads them as K zeros)
__global__ void zero_hs_pad(float* __restrict__ hs)
{
    int idx = blockIdx.x * 256 + threadIdx.x;     // M_ * 14
    if (idx >= M_ * (KP3 - H_)) return;
    int m = idx / (KP3 - H_), j = idx - m * (KP3 - H_);
    hs[(size_t)m * KP3 + H_ + j] = 0.f;
}

// ============ C = A(M x astride) * B^T + tail fixup, via warp mma ============
// AVEC: A rows 8B-aligned with even k offsets -> float2 loads
// CVEC: N even & cols even -> float2 stores
template<int KSTEPS, int NTTOT, bool AVEC, bool CVEC>
__global__ void __launch_bounds__(256)
gemm_mma(const float* __restrict__ A, int astride, int fixk,
         const uint4* __restrict__ bp, const float2* __restrict__ tail,
         float* __restrict__ C, int N)
{
    const int tid  = threadIdx.x, wid = tid >> 5, lane = tid & 31;
    const int wm   = wid & 3, wn = wid >> 2;
    const int m0   = blockIdx.y * 128 + wm * 32;
    const int nt0  = blockIdx.x * 14 + wn * 7;
    const int r    = lane >> 2;
    const int c2   = (lane & 3) * 2;

    float acc[2][7][4] = {};

    for (int kt = 0; kt < KSTEPS; kt++) {
        const int k0 = kt * 16;
        unsigned ah[2][4], al[2][4];
#pragma unroll
        for (int i = 0; i < 2; i++) {
            const float* p0 = A + (size_t)(m0 + i * 16 + r) * astride + k0 + c2;
            const float* p1 = p0 + 8 * astride;
            float v00, v01, v10, v11, v02, v03, v12, v13;
            if (AVEC) {
                float2 q0 = *(const float2*)p0;
                float2 q1 = *(const float2*)p1;
                float2 q2 = *(const float2*)(p0 + 8);
                float2 q3 = *(const float2*)(p1 + 8);
                v00 = q0.x; v01 = q0.y; v10 = q1.x; v11 = q1.y;
                v02 = q2.x; v03 = q2.y; v12 = q3.x; v13 = q3.y;
            } else {
                v00 = p0[0]; v01 = p0[1]; v10 = p1[0]; v11 = p1[1];
                v02 = p0[8]; v03 = p0[9]; v12 = p1[8]; v13 = p1[9];
            }
            split2(v00, v01, ah[i][0], al[i][0]);
            split2(v10, v11, ah[i][1], al[i][1]);
            split2(v02, v03, ah[i][2], al[i][2]);
            split2(v12, v13, ah[i][3], al[i][3]);
        }
        const uint4* bb = bp + ((size_t)kt * NTTOT + nt0) * 32 + lane;
#pragma unroll
        for (int t = 0; t < 7; t++) {
            uint4 b = bb[t * 32];
#pragma unroll
            for (int i = 0; i < 2; i++) {
                mma16816(acc[i][t], ah[i], b.x, b.y);   // hi * hi
                mma16816(acc[i][t], ah[i], b.z, b.w);   // hi * lo
                mma16816(acc[i][t], al[i], b.x, b.y);   // lo * hi
            }
        }
    }

#pragma unroll
    for (int i = 0; i < 2; i++) {
        const int r0 = m0 + i * 16 + r, r1 = r0 + 8;
        const float xa = A[(size_t)r0 * astride + fixk];
        const float xb = A[(size_t)r1 * astride + fixk];
        float* C0 = C + (size_t)r0 * N;
        float* C1 = C + (size_t)r1 * N;
#pragma unroll
        for (int t = 0; t < 7; t++) {
            int col = (nt0 + t) * 8 + c2;
            if (CVEC) {
                if (col < N) {   // N even, col even -> col+1 < N too
                    float2 tw0 = tail[col], tw1 = tail[col + 1];
                    float2 o0 = make_float2(acc[i][t][0] + xa * tw0.x + tw0.y,
                                            acc[i][t][1] + xa * tw1.x + tw1.y);
                    float2 o1 = make_float2(acc[i][t][2] + xb * tw0.x + tw0.y,
                                            acc[i][t][3] + xb * tw1.x + tw1.y);
                    *(float2*)(C0 + col) = o0;
                    *(float2*)(C1 + col) = o1;
                }
            } else {
                if (col < N) {
                    float2 tw = tail[col];
                    C0[col] = acc[i][t][0] + xa * tw.x + tw.y;
                    C1[col] = acc[i][t][2] + xb * tw.x + tw.y;
                }
                if (col + 1 < N) {
                    float2 tw = tail[col + 1];
                    C0[col + 1] = acc[i][t][1] + xa * tw.x + tw.y;
                    C1[col + 1] = acc[i][t][3] + xb * tw.x + tw.y;
                }
            }
        }
    }
}

// ================= LSTM recurrence over the BATCH axis =================
// 128 CTAs x 448 threads = 2 groups x 224 (7 warps). Each group: 2 lanes,
// 64 steps, own named barrier. h stored as float4 k-pairs so one LDS.128
// feeds both lanes' FMA2. Accumulator chains split x2.
__device__ __forceinline__ float sigm_f(float x) { return 1.f / (1.f + __expf(-x)); }
__device__ __forceinline__ float tanh_f(float x) { return 2.f / (1.f + __expf(-2.f * x)) - 1.f; }

__global__ void __launch_bounds__(448)
lstm_rec_kernel(const float* __restrict__ xg, const float* __restrict__ W_hh,
                const float* __restrict__ b_hh, float* __restrict__ hs)
{
    __shared__ __align__(16) float4 h4p[2][25];      // [grp][kpair] = {l0e,l0o,l1e,l1o}
    __shared__ __align__(8)  float2 gsh[2][G_];      // [grp][gate]  = {lane0, lane1}

    const int tid   = threadIdx.x;
    const int grp   = tid / 224;
    const int lt    = tid - grp * 224;
    const int lane0 = blockIdx.x * 4 + grp * 2;
    const int barid = grp + 1;

    u64 wp[25];
    float bh = 0.f;
    if (lt < G_) {
        const float* wr = W_hh + lt * H_;
#pragma unroll
        for (int kk = 0; kk < 25; kk++) wp[kk] = pk2(wr[2 * kk], wr[2 * kk + 1]);
        bh = b_hh[lt];
    }
    if (lt < 25) h4p[grp][lt] = make_float4(0.f, 0.f, 0.f, 0.f);
    float c = 0.f;
    __syncthreads();

    float xc0 = 0.f, xc1 = 0.f;
    if (lt < G_) {
        const float* xr = xg + (size_t)lane0 * G_ + lt;
        xc0 = xr[0]; xc1 = xr[G_];
    }

    for (int b = 0; b < B_; b++) {
        float xn0 = 0.f, xn1 = 0.f;
        if (lt < G_ && b + 1 < B_) {
            const float* xr = xg + (size_t)((b + 1) * T_ + lane0) * G_ + lt;
            xn0 = xr[0]; xn1 = xr[G_];
        }

        if (lt < G_) {
            // acc = {sum over even k, sum over odd k}; two chains per lane
            u64 a0 = pk2(xc0 + bh, 0.f), a0b = 0ULL;
            u64 a1 = pk2(xc1 + bh, 0.f), a1b = 0ULL;
#pragma unroll
            for (int kk = 0; kk < 25; kk++) {
                ulonglong2 hv = *(const ulonglong2*)&h4p[grp][kk];
                if (kk & 1) { fma2(a0b, hv.x, wp[kk]); fma2(a1b, hv.y, wp[kk]); }
                else        { fma2(a0,  hv.x, wp[kk]); fma2(a1,  hv.y, wp[kk]); }
            }
            add2(a0, a0b);
            add2(a1, a1b);
            float e0, e1, f0, f1;
            upk2(a0, e0, e1);
            upk2(a1, f0, f1);
            gsh[grp][lt] = make_float2(e0 + e1, f0 + f1);
        }
        asm volatile("bar.sync %0, 224;" :: "r"(barid) : "memory");

        if (lt < 2 * H_) {                    // 100 update threads: (lane l, unit hh)
            int l  = lt & 1;
            int hh = lt >> 1;
            const float* gp = (const float*)gsh[grp];
            float ig = gp[2 * hh            + l];
            float fg = gp[2 * (H_ + hh)     + l];
            float gg = gp[2 * (2 * H_ + hh) + l];
            float og = gp[2 * (3 * H_ + hh) + l];
            float si = sigm_f(ig);
            float sf = sigm_f(fg);
            float so = sigm_f(og);
            c = sf * c + si * tanh_f(gg);
            float h2 = so * tanh_f(c);
            ((float*)&h4p[grp][hh >> 1])[2 * l + (hh & 1)] = h2;
            hs[(size_t)(b * T_ + lane0 + l) * KP3 + hh] = h2;
        }
        asm volatile("bar.sync %0, 224;" :: "r"(barid) : "memory");

        xc0 = xn0; xc1 = xn1;
    }
}

// ---------------- launch ----------------
extern "C" void kernel_launch(void* const* d_in, const int* in_sizes, int n_in,
                              void* d_out, int out_size)
{
    const float* x     = (const float*)d_in[0];
    const float* W_ih  = (const float*)d_in[1];
    const float* W_hh  = (const float*)d_in[2];
    const float* b_ih  = (const float*)d_in[3];
    const float* b_hh  = (const float*)d_in[4];
    const float* W_out = (const float*)d_in[5];
    const float* b_out = (const float*)d_in[6];
    float* out = (float*)d_out;

    float *xg, *hs;
    uint4 *b1, *b3;
    float2 *t1, *t3;
    cudaGetSymbolAddress((void**)&xg, g_xg);
    cudaGetSymbolAddress((void**)&hs, g_hs);
    cudaGetSymbolAddress((void**)&b1, g_b1);
    cudaGetSymbolAddress((void**)&b3, g_b3);
    cudaGetSymbolAddress((void**)&t1, g_tail1);
    cudaGetSymbolAddress((void**)&t3, g_tail3);

    // 0) pack weight fragments + zero hs pad cols (all tiny)
    pack_b1<<<(G1_KS * G1_NT * 32 + 255) / 256, 256>>>(W_ih, b1, b_ih, t1);
    pack_b3<<<(G3_KS * G3_NT * 32 + 255) / 256, 256>>>(W_out, b3, b_out, t3);
    zero_hs_pad<<<(M_ * (KP3 - H_) + 255) / 256, 256>>>(hs);

    // 1) xg = x @ W_ih^T + b_ih   (split-bf16 warp mma, K=512 + rank-1 col 512)
    gemm_mma<G1_KS, G1_NT, false, true><<<dim3(2, 256), 256>>>(x, F_, 512, b1, t1, xg, G_);

    // 2) batch-axis LSTM recurrence -> hs (32768 x 64 padded)
    lstm_rec_kernel<<<T_ / 4, 448>>>(xg, W_hh, b_hh, hs);

    // 3) out = hs @ W_out^T + b_out (split-bf16 warp mma, K=64)
    gemm_mma<G3_KS, G3_NT, true, false><<<dim3(5, 256), 256>>>(hs, KP3, 0, b3, t3, out, F_);
}

// round 15
// speedup vs baseline: 1.0083x; 1.0083x over previous
#include <cuda_runtime.h>
#include <cuda_bf16.h>
#include <math.h>

// Problem constants
#define B_   64
#define T_   512
#define H_   50
#define G_   200      // 4*H
#define F_   513
#define M_   (B_*T_)  // 32768
#define KP3  64       // H padded for gemm3 A rows

// GEMM1: N padded to 224 (2 n-CTAs x 112), K=512 via 32 k16 steps + fp32 rank-1 fixup (col 512)
#define G1_KS 32
#define G1_NT 28
// GEMM3: N padded to 560 (5 n-CTAs x 112), K=64 -> 4 k16 steps
#define G3_KS 4
#define G3_NT 70

// Scratch (device globals)
__device__ float  g_xg[(size_t)M_ * G_];
__device__ float  g_hs[(size_t)M_ * KP3];
__device__ uint4  g_b1[G1_KS * G1_NT * 32];
__device__ uint4  g_b3[G3_KS * G3_NT * 32];
__device__ float2 g_tail1[224];
__device__ float2 g_tail3[560];

typedef unsigned long long u64;

// ---------------- f32x2 helpers ----------------
__device__ __forceinline__ u64 pk2(float lo, float hi) {
    u64 r; asm("mov.b64 %0, {%1, %2};" : "=l"(r) : "f"(lo), "f"(hi)); return r;
}
__device__ __forceinline__ void upk2(u64 v, float& lo, float& hi) {
    asm("mov.b64 {%0, %1}, %2;" : "=f"(lo), "=f"(hi) : "l"(v));
}
__device__ __forceinline__ void fma2(u64& d, u64 a, u64 b) {
    asm("fma.rn.f32x2 %0, %1, %2, %0;" : "+l"(d) : "l"(a), "l"(b));
}
__device__ __forceinline__ void add2(u64& d, u64 a) {
    asm("add.rn.f32x2 %0, %0, %1;" : "+l"(d) : "l"(a));
}

// ---------------- bf16 split helpers ----------------
__device__ __forceinline__ void split2(float v0, float v1, unsigned& h, unsigned& l) {
    __nv_bfloat162 bh = __float22bfloat162_rn(make_float2(v0, v1));
    h = *(unsigned*)&bh;
    float f0 = __uint_as_float(h << 16);
    float f1 = __uint_as_float(h & 0xffff0000u);
    __nv_bfloat162 bl = __float22bfloat162_rn(make_float2(v0 - f0, v1 - f1));
    l = *(unsigned*)&bl;
}

// ---------------- warp MMA m16n8k16 bf16 ----------------
__device__ __forceinline__ void mma16816(float* d, const unsigned* a,
                                         unsigned b0, unsigned b1) {
    asm volatile(
        "mma.sync.aligned.m16n8k16.row.col.f32.bf16.bf16.f32 "
        "{%0,%1,%2,%3}, {%4,%5,%6,%7}, {%8,%9}, {%0,%1,%2,%3};"
        : "+f"(d[0]), "+f"(d[1]), "+f"(d[2]), "+f"(d[3])
        : "r"(a[0]), "r"(a[1]), "r"(a[2]), "r"(a[3]), "r"(b0), "r"(b1));
}

// ---------------- prepass: pack B fragments ----------------
__global__ void pack_b1(const float* __restrict__ wih, uint4* __restrict__ bp,
                        const float* __restrict__ bih, float2* __restrict__ tail)
{
    int idx = blockIdx.x * 256 + threadIdx.x;
    if (idx < 224)
        tail[idx] = (idx < G_) ? make_float2(wih[idx * F_ + 512], bih[idx])
                               : make_float2(0.f, 0.f);
    if (idx >= G1_KS * G1_NT * 32) return;
    int kt   = idx / (G1_NT * 32);
    int rem  = idx - kt * (G1_NT * 32);
    int lane = rem & 31;
    int nt   = rem >> 5;
    int n    = nt * 8 + (lane >> 2);
    int k0   = kt * 16 + (lane & 3) * 2;
    float v0 = 0.f, v1 = 0.f, v2 = 0.f, v3 = 0.f;
    if (n < G_) {
        const float* wr = wih + (size_t)n * F_;
        v0 = wr[k0]; v1 = wr[k0 + 1]; v2 = wr[k0 + 8]; v3 = wr[k0 + 9];
    }
    unsigned h0, l0, h1, l1;
    split2(v0, v1, h0, l0);
    split2(v2, v3, h1, l1);
    bp[idx] = make_uint4(h0, h1, l0, l1);
}

__global__ void pack_b3(const float* __restrict__ wout, uint4* __restrict__ bp,
                        const float* __restrict__ bout, float2* __restrict__ tail)
{
    int idx = blockIdx.x * 256 + threadIdx.x;
    if (idx < 560)
        tail[idx] = make_float2(0.f, (idx < F_) ? bout[idx] : 0.f);
    if (idx >= G3_KS * G3_NT * 32) return;
    int kt   = idx / (G3_NT * 32);
    int rem  = idx - kt * (G3_NT * 32);
    int lane = rem & 31;
    int nt   = rem >> 5;
    int n    = nt * 8 + (lane >> 2);
    int k0   = kt * 16 + (lane & 3) * 2;
    float v0 = 0.f, v1 = 0.f, v2 = 0.f, v3 = 0.f;
    if (n < F_) {
        const float* wr = wout + (size_t)n * H_;
        if (k0     < H_) v0 = wr[k0];
        if (k0 + 1 < H_) v1 = wr[k0 + 1];
        if (k0 + 8 < H_) v2 = wr[k0 + 8];
        if (k0 + 9 < H_) v3 = wr[k0 + 9];
    }
    unsigned h0, l0, h1, l1;
    split2(v0, v1, h0, l0);
    split2(v2, v3, h1, l1);
    bp[idx] = make_uint4(h0, h1, l0, l1);
}

// zero hs pad columns [H_, KP3) once (gemm3 reads them as K zeros)
__global__ void zero_hs_pad(float* __restrict__ hs)
{
    int idx = blockIdx.x * 256 + threadIdx.x;     // M_ * 14
    if (idx >= M_ * (KP3 - H_)) return;
    int m = idx / (KP3 - H_), j = idx - m * (KP3 - H_);
    hs[(size_t)m * KP3 + H_ + j] = 0.f;
}

// ============ C = A(M x astride) * B^T + tail fixup, via warp mma ============
// AVEC: A rows 8B-aligned with even k offsets -> float2 loads
// CVEC: N even & cols even -> float2 stores
template<int KSTEPS, int NTTOT, bool AVEC, bool CVEC>
__global__ void __launch_bounds__(256)
gemm_mma(const float* __restrict__ A, int astride, int fixk,
         const uint4* __restrict__ bp, const float2* __restrict__ tail,
         float* __restrict__ C, int N)
{
    const int tid  = threadIdx.x, wid = tid >> 5, lane = tid & 31;
    const int wm   = wid & 3, wn = wid >> 2;
    const int m0   = blockIdx.y * 128 + wm * 32;
    const int nt0  = blockIdx.x * 14 + wn * 7;
    const int r    = lane >> 2;
    const int c2   = (lane & 3) * 2;

    float acc[2][7][4] = {};

    for (int kt = 0; kt < KSTEPS; kt++) {
        const int k0 = kt * 16;
        unsigned ah[2][4], al[2][4];
#pragma unroll
        for (int i = 0; i < 2; i++) {
            const float* p0 = A + (size_t)(m0 + i * 16 + r) * astride + k0 + c2;
            const float* p1 = p0 + 8 * astride;
            float v00, v01, v10, v11, v02, v03, v12, v13;
            if (AVEC) {
                float2 q0 = *(const float2*)p0;
                float2 q1 = *(const float2*)p1;
                float2 q2 = *(const float2*)(p0 + 8);
                float2 q3 = *(const float2*)(p1 + 8);
                v00 = q0.x; v01 = q0.y; v10 = q1.x; v11 = q1.y;
                v02 = q2.x; v03 = q2.y; v12 = q3.x; v13 = q3.y;
            } else {
                v00 = p0[0]; v01 = p0[1]; v10 = p1[0]; v11 = p1[1];
                v02 = p0[8]; v03 = p0[9]; v12 = p1[8]; v13 = p1[9];
            }
            split2(v00, v01, ah[i][0], al[i][0]);
            split2(v10, v11, ah[i][1], al[i][1]);
            split2(v02, v03, ah[i][2], al[i][2]);
            split2(v12, v13, ah[i][3], al[i][3]);
        }
        const uint4* bb = bp + ((size_t)kt * NTTOT + nt0) * 32 + lane;
#pragma unroll
        for (int t = 0; t < 7; t++) {
            uint4 b = bb[t * 32];
#pragma unroll
            for (int i = 0; i < 2; i++) {
                mma16816(acc[i][t], ah[i], b.x, b.y);   // hi * hi
                mma16816(acc[i][t], ah[i], b.z, b.w);   // hi * lo
                mma16816(acc[i][t], al[i], b.x, b.y);   // lo * hi
            }
        }
    }

#pragma unroll
    for (int i = 0; i < 2; i++) {
        const int r0 = m0 + i * 16 + r, r1 = r0 + 8;
        const float xa = A[(size_t)r0 * astride + fixk];
        const float xb = A[(size_t)r1 * astride + fixk];
        float* C0 = C + (size_t)r0 * N;
        float* C1 = C + (size_t)r1 * N;
#pragma unroll
        for (int t = 0; t < 7; t++) {
            int col = (nt0 + t) * 8 + c2;
            if (CVEC) {
                if (col < N) {   // N even, col even -> col+1 < N too
                    float2 tw0 = tail[col], tw1 = tail[col + 1];
                    float2 o0 = make_float2(acc[i][t][0] + xa * tw0.x + tw0.y,
                                            acc[i][t][1] + xa * tw1.x + tw1.y);
                    float2 o1 = make_float2(acc[i][t][2] + xb * tw0.x + tw0.y,
                                            acc[i][t][3] + xb * tw1.x + tw1.y);
                    *(float2*)(C0 + col) = o0;
                    *(float2*)(C1 + col) = o1;
                }
            } else {
                if (col < N) {
                    float2 tw = tail[col];
                    C0[col] = acc[i][t][0] + xa * tw.x + tw.y;
                    C1[col] = acc[i][t][2] + xb * tw.x + tw.y;
                }
                if (col + 1 < N) {
                    float2 tw = tail[col + 1];
                    C0[col + 1] = acc[i][t][1] + xa * tw.x + tw.y;
                    C1[col + 1] = acc[i][t][3] + xb * tw.x + tw.y;
                }
            }
        }
    }
}

// ================= LSTM recurrence over the BATCH axis =================
// 128 CTAs x 448 threads = 2 groups x 224 (7 warps). Each group: 2 lanes,
// 64 steps, own named barrier. h stored as float4 k-pairs so one LDS.128
// feeds both lanes' FMA2. Accumulator chains split x2.
__device__ __forceinline__ float sigm_f(float x) { return 1.f / (1.f + __expf(-x)); }
__device__ __forceinline__ float tanh_f(float x) { return 2.f / (1.f + __expf(-2.f * x)) - 1.f; }

__global__ void __launch_bounds__(448)
lstm_rec_kernel(const float* __restrict__ xg, const float* __restrict__ W_hh,
                const float* __restrict__ b_hh, float* __restrict__ hs)
{
    __shared__ __align__(16) float4 h4p[2][25];      // [grp][kpair] = {l0e,l0o,l1e,l1o}
    __shared__ __align__(8)  float2 gsh[2][G_];      // [grp][gate]  = {lane0, lane1}

    const int tid   = threadIdx.x;
    const int grp   = tid / 224;
    const int lt    = tid - grp * 224;
    const int lane0 = blockIdx.x * 4 + grp * 2;
    const int barid = grp + 1;

    u64 wp[25];
    float bh = 0.f;
    if (lt < G_) {
        const float* wr = W_hh + lt * H_;
#pragma unroll
        for (int kk = 0; kk < 25; kk++) wp[kk] = pk2(wr[2 * kk], wr[2 * kk + 1]);
        bh = b_hh[lt];
    }
    if (lt < 25) h4p[grp][lt] = make_float4(0.f, 0.f, 0.f, 0.f);
    float c = 0.f;
    __syncthreads();

    float xc0 = 0.f, xc1 = 0.f;
    if (lt < G_) {
        const float* xr = xg + (size_t)lane0 * G_ + lt;
        xc0 = xr[0]; xc1 = xr[G_];
    }

    for (int b = 0; b < B_; b++) {
        float xn0 = 0.f, xn1 = 0.f;
        if (lt < G_ && b + 1 < B_) {
            const float* xr = xg + (size_t)((b + 1) * T_ + lane0) * G_ + lt;
            xn0 = xr[0]; xn1 = xr[G_];
        }

        if (lt < G_) {
            // acc = {sum over even k, sum over odd k}; two chains per lane
            u64 a0 = pk2(xc0 + bh, 0.f), a0b = 0ULL;
            u64 a1 = pk2(xc1 + bh, 0.f), a1b = 0ULL;
#pragma unroll
            for (int kk = 0; kk < 25; kk++) {
                ulonglong2 hv = *(const ulonglong2*)&h4p[grp][kk];
                if (kk & 1) { fma2(a0b, hv.x, wp[kk]); fma2(a1b, hv.y, wp[kk]); }
                else        { fma2(a0,  hv.x, wp[kk]); fma2(a1,  hv.y, wp[kk]); }
            }
            add2(a0, a0b);
            add2(a1, a1b);
            float e0, e1, f0, f1;
            upk2(a0, e0, e1);
            upk2(a1, f0, f1);
            gsh[grp][lt] = make_float2(e0 + e1, f0 + f1);
        }
        asm volatile("bar.sync %0, 224;" :: "r"(barid) : "memory");

        if (lt < 2 * H_) {                    // 100 update threads: (lane l, unit hh)
            int l  = lt & 1;
            int hh = lt >> 1;
            const float* gp = (const float*)gsh[grp];
            float ig = gp[2 * hh            + l];
            float fg = gp[2 * (H_ + hh)     + l];
            float gg = gp[2 * (2 * H_ + hh) + l];
            float og = gp[2 * (3 * H_ + hh) + l];
            float si = sigm_f(ig);
            float sf = sigm_f(fg);
            float so = sigm_f(og);
            c = sf * c + si * tanh_f(gg);
            float h2 = so * tanh_f(c);
            ((float*)&h4p[grp][hh >> 1])[2 * l + (hh & 1)] = h2;
            hs[(size_t)(b * T_ + lane0 + l) * KP3 + hh] = h2;
        }
        asm volatile("bar.sync %0, 224;" :: "r"(barid) : "memory");

        xc0 = xn0; xc1 = xn1;
    }
}

// ---------------- launch ----------------
extern "C" void kernel_launch(void* const* d_in, const int* in_sizes, int n_in,
                              void* d_out, int out_size)
{
    const float* x     = (const float*)d_in[0];
    const float* W_ih  = (const float*)d_in[1];
    const float* W_hh  = (const float*)d_in[2];
    const float* b_ih  = (const float*)d_in[3];
    const float* b_hh  = (const float*)d_in[4];
    const float* W_out = (const float*)d_in[5];
    const float* b_out = (const float*)d_in[6];
    float* out = (float*)d_out;

    float *xg, *hs;
    uint4 *b1, *b3;
    float2 *t1, *t3;
    cudaGetSymbolAddress((void**)&xg, g_xg);
    cudaGetSymbolAddress((void**)&hs, g_hs);
    cudaGetSymbolAddress((void**)&b1, g_b1);
    cudaGetSymbolAddress((void**)&b3, g_b3);
    cudaGetSymbolAddress((void**)&t1, g_tail1);
    cudaGetSymbolAddress((void**)&t3, g_tail3);

    // 0) pack weight fragments + zero hs pad cols (all tiny)
    pack_b1<<<(G1_KS * G1_NT * 32 + 255) / 256, 256>>>(W_ih, b1, b_ih, t1);
    pack_b3<<<(G3_KS * G3_NT * 32 + 255) / 256, 256>>>(W_out, b3, b_out, t3);
    zero_hs_pad<<<(M_ * (KP3 - H_) + 255) / 256, 256>>>(hs);

    // 1) xg = x @ W_ih^T + b_ih   (split-bf16 warp mma, K=512 + rank-1 col 512)
    gemm_mma<G1_KS, G1_NT, false, true><<<dim3(2, 256), 256>>>(x, F_, 512, b1, t1, xg, G_);

    // 2) batch-axis LSTM recurrence -> hs (32768 x 64 padded)
    lstm_rec_kernel<<<T_ / 4, 448>>>(xg, W_hh, b_hh, hs);

    // 3) out = hs @ W_out^T + b_out (split-bf16 warp mma, K=64)
    gemm_mma<G3_KS, G3_NT, true, false><<<dim3(5, 256), 256>>>(hs, KP3, 0, b3, t3, out, F_);
}

// round 16
// speedup vs baseline: 1.0084x; 1.0001x over previous
#include <cuda_runtime.h>
#include <cuda_bf16.h>
#include <math.h>

// Problem constants
#define B_   64
#define T_   512
#define H_   50
#define G_   200      // 4*H
#define F_   513
#define M_   (B_*T_)  // 32768
#define KP3  64       // H padded for gemm3 A rows

// GEMM1: N padded to 224 (2 n-CTAs x 112), K=512 via 32 k16 steps + fp32 rank-1 fixup (col 512)
#define G1_KS 32
#define G1_NT 28
// GEMM3: N padded to 560 (5 n-CTAs x 112), K=64 -> 4 k16 steps
#define G3_KS 4
#define G3_NT 70

// Scratch (device globals)
__device__ float  g_xg[(size_t)M_ * G_];
__device__ float  g_hs[(size_t)M_ * KP3];
__device__ uint4  g_b1[G1_KS * G1_NT * 32];
__device__ uint4  g_b3[G3_KS * G3_NT * 32];
__device__ float2 g_tail1[224];
__device__ float2 g_tail3[560];

typedef unsigned long long u64;

// ---------------- f32x2 helpers ----------------
__device__ __forceinline__ u64 pk2(float lo, float hi) {
    u64 r; asm("mov.b64 %0, {%1, %2};" : "=l"(r) : "f"(lo), "f"(hi)); return r;
}
__device__ __forceinline__ void upk2(u64 v, float& lo, float& hi) {
    asm("mov.b64 {%0, %1}, %2;" : "=f"(lo), "=f"(hi) : "l"(v));
}
__device__ __forceinline__ void fma2(u64& d, u64 a, u64 b) {
    asm("fma.rn.f32x2 %0, %1, %2, %0;" : "+l"(d) : "l"(a), "l"(b));
}
__device__ __forceinline__ void add2(u64& d, u64 a) {
    asm("add.rn.f32x2 %0, %0, %1;" : "+l"(d) : "l"(a));
}

// ---------------- bf16 split helpers ----------------
__device__ __forceinline__ void split2(float v0, float v1, unsigned& h, unsigned& l) {
    __nv_bfloat162 bh = __float22bfloat162_rn(make_float2(v0, v1));
    h = *(unsigned*)&bh;
    float f0 = __uint_as_float(h << 16);
    float f1 = __uint_as_float(h & 0xffff0000u);
    __nv_bfloat162 bl = __float22bfloat162_rn(make_float2(v0 - f0, v1 - f1));
    l = *(unsigned*)&bl;
}

// ---------------- warp MMA m16n8k16 bf16 ----------------
__device__ __forceinline__ void mma16816(float* d, const unsigned* a,
                                         unsigned b0, unsigned b1) {
    asm volatile(
        "mma.sync.aligned.m16n8k16.row.col.f32.bf16.bf16.f32 "
        "{%0,%1,%2,%3}, {%4,%5,%6,%7}, {%8,%9}, {%0,%1,%2,%3};"
        : "+f"(d[0]), "+f"(d[1]), "+f"(d[2]), "+f"(d[3])
        : "r"(a[0]), "r"(a[1]), "r"(a[2]), "r"(a[3]), "r"(b0), "r"(b1));
}

// ---------------- prepass: pack B fragments ----------------
__global__ void pack_b1(const float* __restrict__ wih, uint4* __restrict__ bp,
                        const float* __restrict__ bih, float2* __restrict__ tail)
{
    int idx = blockIdx.x * 256 + threadIdx.x;
    if (idx < 224)
        tail[idx] = (idx < G_) ? make_float2(wih[idx * F_ + 512], bih[idx])
                               : make_float2(0.f, 0.f);
    if (idx >= G1_KS * G1_NT * 32) return;
    int kt   = idx / (G1_NT * 32);
    int rem  = idx - kt * (G1_NT * 32);
    int lane = rem & 31;
    int nt   = rem >> 5;
    int n    = nt * 8 + (lane >> 2);
    int k0   = kt * 16 + (lane & 3) * 2;
    float v0 = 0.f, v1 = 0.f, v2 = 0.f, v3 = 0.f;
    if (n < G_) {
        const float* wr = wih + (size_t)n * F_;
        v0 = wr[k0]; v1 = wr[k0 + 1]; v2 = wr[k0 + 8]; v3 = wr[k0 + 9];
    }
    unsigned h0, l0, h1, l1;
    split2(v0, v1, h0, l0);
    split2(v2, v3, h1, l1);
    bp[idx] = make_uint4(h0, h1, l0, l1);
}

__global__ void pack_b3(const float* __restrict__ wout, uint4* __restrict__ bp,
                        const float* __restrict__ bout, float2* __restrict__ tail)
{
    int idx = blockIdx.x * 256 + threadIdx.x;
    if (idx < 560)
        tail[idx] = make_float2(0.f, (idx < F_) ? bout[idx] : 0.f);
    if (idx >= G3_KS * G3_NT * 32) return;
    int kt   = idx / (G3_NT * 32);
    int rem  = idx - kt * (G3_NT * 32);
    int lane = rem & 31;
    int nt   = rem >> 5;
    int n    = nt * 8 + (lane >> 2);
    int k0   = kt * 16 + (lane & 3) * 2;
    float v0 = 0.f, v1 = 0.f, v2 = 0.f, v3 = 0.f;
    if (n < F_) {
        const float* wr = wout + (size_t)n * H_;
        if (k0     < H_) v0 = wr[k0];
        if (k0 + 1 < H_) v1 = wr[k0 + 1];
        if (k0 + 8 < H_) v2 = wr[k0 + 8];
        if (k0 + 9 < H_) v3 = wr[k0 + 9];
    }
    unsigned h0, l0, h1, l1;
    split2(v0, v1, h0, l0);
    split2(v2, v3, h1, l1);
    bp[idx] = make_uint4(h0, h1, l0, l1);
}

// zero hs pad columns [H_, KP3) once (gemm3 reads them as K zeros)
__global__ void zero_hs_pad(float* __restrict__ hs)
{
    int idx = blockIdx.x * 256 + threadIdx.x;     // M_ * 14
    if (idx >= M_ * (KP3 - H_)) return;
    int m = idx / (KP3 - H_), j = idx - m * (KP3 - H_);
    hs[(size_t)m * KP3 + H_ + j] = 0.f;
}

// ============ C = A(M x astride) * B^T + tail fixup, via warp mma ============
// AVEC: A rows 8B-aligned with even k offsets -> float2 loads
// CVEC: N even & cols even -> float2 stores
template<int KSTEPS, int NTTOT, bool AVEC, bool CVEC>
__global__ void __launch_bounds__(256)
gemm_mma(const float* __restrict__ A, int astride, int fixk,
         const uint4* __restrict__ bp, const float2* __restrict__ tail,
         float* __restrict__ C, int N)
{
    const int tid  = threadIdx.x, wid = tid >> 5, lane = tid & 31;
    const int wm   = wid & 3, wn = wid >> 2;
    const int m0   = blockIdx.y * 128 + wm * 32;
    const int nt0  = blockIdx.x * 14 + wn * 7;
    const int r    = lane >> 2;
    const int c2   = (lane & 3) * 2;

    float acc[2][7][4] = {};

    for (int kt = 0; kt < KSTEPS; kt++) {
        const int k0 = kt * 16;
        unsigned ah[2][4], al[2][4];
#pragma unroll
        for (int i = 0; i < 2; i++) {
            const float* p0 = A + (size_t)(m0 + i * 16 + r) * astride + k0 + c2;
            const float* p1 = p0 + 8 * astride;
            float v00, v01, v10, v11, v02, v03, v12, v13;
            if (AVEC) {
                float2 q0 = *(const float2*)p0;
                float2 q1 = *(const float2*)p1;
                float2 q2 = *(const float2*)(p0 + 8);
                float2 q3 = *(const float2*)(p1 + 8);
                v00 = q0.x; v01 = q0.y; v10 = q1.x; v11 = q1.y;
                v02 = q2.x; v03 = q2.y; v12 = q3.x; v13 = q3.y;
            } else {
                v00 = p0[0]; v01 = p0[1]; v10 = p1[0]; v11 = p1[1];
                v02 = p0[8]; v03 = p0[9]; v12 = p1[8]; v13 = p1[9];
            }
            split2(v00, v01, ah[i][0], al[i][0]);
            split2(v10, v11, ah[i][1], al[i][1]);
            split2(v02, v03, ah[i][2], al[i][2]);
            split2(v12, v13, ah[i][3], al[i][3]);
        }
        const uint4* bb = bp + ((size_t)kt * NTTOT + nt0) * 32 + lane;
#pragma unroll
        for (int t = 0; t < 7; t++) {
            uint4 b = bb[t * 32];
#pragma unroll
            for (int i = 0; i < 2; i++) {
                mma16816(acc[i][t], ah[i], b.x, b.y);   // hi * hi
                mma16816(acc[i][t], ah[i], b.z, b.w);   // hi * lo
                mma16816(acc[i][t], al[i], b.x, b.y);   // lo * hi
            }
        }
    }

#pragma unroll
    for (int i = 0; i < 2; i++) {
        const int r0 = m0 + i * 16 + r, r1 = r0 + 8;
        const float xa = A[(size_t)r0 * astride + fixk];
        const float xb = A[(size_t)r1 * astride + fixk];
        float* C0 = C + (size_t)r0 * N;
        float* C1 = C + (size_t)r1 * N;
#pragma unroll
        for (int t = 0; t < 7; t++) {
            int col = (nt0 + t) * 8 + c2;
            if (CVEC) {
                if (col < N) {   // N even, col even -> col+1 < N too
                    float2 tw0 = tail[col], tw1 = tail[col + 1];
                    float2 o0 = make_float2(acc[i][t][0] + xa * tw0.x + tw0.y,
                                            acc[i][t][1] + xa * tw1.x + tw1.y);
                    float2 o1 = make_float2(acc[i][t][2] + xb * tw0.x + tw0.y,
                                            acc[i][t][3] + xb * tw1.x + tw1.y);
                    *(float2*)(C0 + col) = o0;
                    *(float2*)(C1 + col) = o1;
                }
            } else {
                if (col < N) {
                    float2 tw = tail[col];
                    C0[col] = acc[i][t][0] + xa * tw.x + tw.y;
                    C1[col] = acc[i][t][2] + xb * tw.x + tw.y;
                }
                if (col + 1 < N) {
                    float2 tw = tail[col + 1];
                    C0[col + 1] = acc[i][t][1] + xa * tw.x + tw.y;
                    C1[col + 1] = acc[i][t][3] + xb * tw.x + tw.y;
                }
            }
        }
    }
}

// ================= LSTM recurrence over the BATCH axis =================
// 128 CTAs x 448 threads = 2 groups x 224 (7 warps). Each group: 2 lanes,
// 64 steps, own named barrier. h stored as float4 k-pairs so one LDS.128
// feeds both lanes' FMA2. Accumulator chains split x2.
__device__ __forceinline__ float sigm_f(float x) { return 1.f / (1.f + __expf(-x)); }
__device__ __forceinline__ float tanh_f(float x) { return 2.f / (1.f + __expf(-2.f * x)) - 1.f; }

__global__ void __launch_bounds__(448)
lstm_rec_kernel(const float* __restrict__ xg, const float* __restrict__ W_hh,
                const float* __restrict__ b_hh, float* __restrict__ hs)
{
    __shared__ __align__(16) float4 h4p[2][25];      // [grp][kpair] = {l0e,l0o,l1e,l1o}
    __shared__ __align__(8)  float2 gsh[2][G_];      // [grp][gate]  = {lane0, lane1}

    const int tid   = threadIdx.x;
    const int grp   = tid / 224;
    const int lt    = tid - grp * 224;
    const int lane0 = blockIdx.x * 4 + grp * 2;
    const int barid = grp + 1;

    u64 wp[25];
    float bh = 0.f;
    if (lt < G_) {
        const float* wr = W_hh + lt * H_;
#pragma unroll
        for (int kk = 0; kk < 25; kk++) wp[kk] = pk2(wr[2 * kk], wr[2 * kk + 1]);
        bh = b_hh[lt];
    }
    if (lt < 25) h4p[grp][lt] = make_float4(0.f, 0.f, 0.f, 0.f);
    float c = 0.f;
    __syncthreads();

    float xc0 = 0.f, xc1 = 0.f;
    if (lt < G_) {
        const float* xr = xg + (size_t)lane0 * G_ + lt;
        xc0 = xr[0]; xc1 = xr[G_];
    }

    for (int b = 0; b < B_; b++) {
        float xn0 = 0.f, xn1 = 0.f;
        if (lt < G_ && b + 1 < B_) {
            const float* xr = xg + (size_t)((b + 1) * T_ + lane0) * G_ + lt;
            xn0 = xr[0]; xn1 = xr[G_];
        }

        if (lt < G_) {
            // acc = {sum over even k, sum over odd k}; two chains per lane
            u64 a0 = pk2(xc0 + bh, 0.f), a0b = 0ULL;
            u64 a1 = pk2(xc1 + bh, 0.f), a1b = 0ULL;
#pragma unroll
            for (int kk = 0; kk < 25; kk++) {
                ulonglong2 hv = *(const ulonglong2*)&h4p[grp][kk];
                if (kk & 1) { fma2(a0b, hv.x, wp[kk]); fma2(a1b, hv.y, wp[kk]); }
                else        { fma2(a0,  hv.x, wp[kk]); fma2(a1,  hv.y, wp[kk]); }
            }
            add2(a0, a0b);
            add2(a1, a1b);
            float e0, e1, f0, f1;
            upk2(a0, e0, e1);
            upk2(a1, f0, f1);
            gsh[grp][lt] = make_float2(e0 + e1, f0 + f1);
        }
        asm volatile("bar.sync %0, 224;" :: "r"(barid) : "memory");

        if (lt < 2 * H_) {                    // 100 update threads: (lane l, unit hh)
            int l  = lt & 1;
            int hh = lt >> 1;
            const float* gp = (const float*)gsh[grp];
            float ig = gp[2 * hh            + l];
            float fg = gp[2 * (H_ + hh)     + l];
            float gg = gp[2 * (2 * H_ + hh) + l];
            float og = gp[2 * (3 * H_ + hh) + l];
            float si = sigm_f(ig);
            float sf = sigm_f(fg);
            float so = sigm_f(og);
            c = sf * c + si * tanh_f(gg);
            float h2 = so * tanh_f(c);
            ((float*)&h4p[grp][hh >> 1])[2 * l + (hh & 1)] = h2;
            hs[(size_t)(b * T_ + lane0 + l) * KP3 + hh] = h2;
        }
        asm volatile("bar.sync %0, 224;" :: "r"(barid) : "memory");

        xc0 = xn0; xc1 = xn1;
    }
}

// ---------------- launch ----------------
extern "C" void kernel_launch(void* const* d_in, const int* in_sizes, int n_in,
                              void* d_out, int out_size)
{
    const float* x     = (const float*)d_in[0];
    const float* W_ih  = (const float*)d_in[1];
    const float* W_hh  = (const float*)d_in[2];
    const float* b_ih  = (const float*)d_in[3];
    const float* b_hh  = (const float*)d_in[4];
    const float* W_out = (const float*)d_in[5];
    const float* b_out = (const float*)d_in[6];
    float* out = (float*)d_out;

    float *xg, *hs;
    uint4 *b1, *b3;
    float2 *t1, *t3;
    cudaGetSymbolAddress((void**)&xg, g_xg);
    cudaGetSymbolAddress((void**)&hs, g_hs);
    cudaGetSymbolAddress((void**)&b1, g_b1);
    cudaGetSymbolAddress((void**)&b3, g_b3);
    cudaGetSymbolAddress((void**)&t1, g_tail1);
    cudaGetSymbolAddress((void**)&t3, g_tail3);

    // 0) pack weight fragments + zero hs pad cols (all tiny)
    pack_b1<<<(G1_KS * G1_NT * 32 + 255) / 256, 256>>>(W_ih, b1, b_ih, t1);
    pack_b3<<<(G3_KS * G3_NT * 32 + 255) / 256, 256>>>(W_out, b3, b_out, t3);
    zero_hs_pad<<<(M_ * (KP3 - H_) + 255) / 256, 256>>>(hs);

    // 1) xg = x @ W_ih^T + b_ih   (split-bf16 warp mma, K=512 + rank-1 col 512)
    gemm_mma<G1_KS, G1_NT, false, true><<<dim3(2, 256), 256>>>(x, F_, 512, b1, t1, xg, G_);

    // 2) batch-axis LSTM recurrence -> hs (32768 x 64 padded)
    lstm_rec_kernel<<<T_ / 4, 448>>>(xg, W_hh, b_hh, hs);

    // 3) out = hs @ W_out^T + b_out (split-bf16 warp mma, K=64)
    gemm_mma<G3_KS, G3_NT, true, false><<<dim3(5, 256), 256>>>(hs, KP3, 0, b3, t3, out, F_);
}